// round 9
// baseline (speedup 1.0000x reference)
#include <cuda_runtime.h>
#include <cstdint>

// CARAFE: B=8, C=256, H=W=64, K=5, UP=2.
// out[b,c,2h+i,2w+j] = sum_{ki,kj} km[b,(i*2+j)*25+ki*5+kj,h,w] * x[b,c,h+ki-2,w+kj-2]
//
// R8 vs R7 (60.1us): WARP-PRIVATE staging -> ZERO __syncthreads.
//  - each warp (32 pixels) stages its own 40-float-wide window (float4-aligned,
//    9 cp.async16 per row, 4-col overlap with sibling warp)
//  - all producer/consumer ordering is same-warp program order + __syncwarp;
//    warps drift freely -> FFMA pipe fed continuously (floor 48.4us)
//  - h-halo rows zero-filled by cp.async src-size=0; the 2 永久-zero w-halo
//    float4s per row pre-zeroed once (staging never touches them)
// Compute loop unchanged: 25 LDS + 100 scalar FFMA per channel, weights in regs.

namespace {
constexpr int Hc = 64, Wc = 64, Cc = 256, Bc = 8;
constexpr int Kk = 5, QQ = 100;
constexpr int CPC = 4;                   // channels per iteration
constexpr int THREADS = 128;
constexpr int NITER = 64 / CPC;          // 16
constexpr int WROW = 40;                 // staged floats per row per warp (aligned)
constexpr int BUFFLOATS = CPC * Kk * WROW;     // 800 floats per buffer
constexpr int NBUF = 2;
constexpr int WARPFLOATS = NBUF * BUFFLOATS;   // 1600
constexpr int NTASK = 6;                 // cp.async tasks per lane (last predicated)
constexpr int TASKS = CPC * Kk * 9;      // 180 staged float4 per warp per group
constexpr int CH4 = Hc * Wc / 4;         // 1024 float4 per channel image
}

__device__ __forceinline__ void cp_async16(uint32_t dst, const float4* src, bool valid) {
    int sz = valid ? 16 : 0;
    asm volatile("cp.async.cg.shared.global [%0], [%1], 16, %2;"
                 :: "r"(dst), "l"(src), "r"(sz) : "memory");
}
__device__ __forceinline__ void cp_commit() {
    asm volatile("cp.async.commit_group;" ::: "memory");
}
template <int N>
__device__ __forceinline__ void cp_wait() {
    asm volatile("cp.async.wait_group %0;" :: "n"(N) : "memory");
}

__global__ __launch_bounds__(THREADS, 4)
void carafe_kernel(const float* __restrict__ x,
                   const float* __restrict__ km,
                   float* __restrict__ out)
{
    const int bh = blockIdx.x;           // 0..511
    const int b  = bh >> 6;
    const int h  = bh & 63;
    const int cbase = blockIdx.y << 7;   // 0 or 128
    const int tid  = threadIdx.x;
    const int lane = tid & 31;
    const int warp = tid >> 5;
    const int p = warp & 1;              // pixel half: w in [32p, 32p+32)
    const int s = warp >> 1;             // channel slice 0/1
    const int w = (p << 5) + lane;

    __shared__ __align__(16) float sbuf[4 * WARPFLOATS];   // [warp][buf][800]

    float* wbase = &sbuf[warp * WARPFLOATS];
    const uint32_t wb_u32 = (uint32_t)__cvta_generic_to_shared(wbase);

    // ---- pre-zero the permanently-zero w-halo float4 per row (both buffers) ----
    // warp window covers global cols [32p-4, 32p+36); for p=0 f4#0 (cols -4..-1)
    // and for p=1 f4#9 (cols 64..67) are always outside the image.
    const int fzero = p ? 9 : 0;
    for (int t = lane; t < NBUF * CPC * Kk; t += 32) {
        int bb  = t / (CPC * Kk);
        int rem = t - bb * (CPC * Kk);
        int ci  = rem / Kk, r = rem - ci * Kk;
        float4* z = (float4*)(wbase + bb * BUFFLOATS + (ci * Kk + r) * WROW + 4 * fzero);
        *z = make_float4(0.f, 0.f, 0.f, 0.f);
    }

    const float4* xb4 = (const float4*)(x + (size_t)b * Cc * Hc * Wc);

    // ---- per-lane staging tasks: 6 fixed cp.async16 (task 5 predicated) ----
    const bool t5 = (lane + 32 * 5) < TASKS;     // lanes 0..19
    int      sidx[NTASK];
    uint32_t sdst[NTASK];
    bool     sval[NTASK];
    #pragma unroll
    for (int k = 0; k < NTASK; k++) {
        int t = lane + 32 * k; if (t >= TASKS) t = 0;   // dummy for predicated-off
        int ci  = t / 45;  int rem = t - ci * 45;
        int r   = rem / 9; int f9  = rem - r * 9;
        int f    = f9 + (p ? 0 : 1);         // staged f4 slots: p=0 -> 1..9, p=1 -> 0..8
        int col4 = (p << 3) - 1 + f;         // global float4 column, in [0,16)
        int gr   = h - 2 + r;
        bool grv = (unsigned)gr < (unsigned)Hc;
        sval[k] = grv;                       // zero-fill h-halo via src-size=0
        sidx[k] = (cbase + (s << 6) + ci) * CH4 + (grv ? gr : 0) * (Wc / 4) + col4;
        sdst[k] = wb_u32 + ((ci * Kk + r) * WROW + 4 * f) * 4;
    }

    // ---- prologue: issue groups 0 (buf0) and 1 (buf1) before weight loads ----
    #pragma unroll
    for (int k = 0; k < NTASK; k++)
        if (k < 5 || t5) cp_async16(sdst[k], xb4 + sidx[k], sval[k]);
    cp_commit();
    #pragma unroll
    for (int k = 0; k < NTASK; k++) sidx[k] += CPC * CH4;
    #pragma unroll
    for (int k = 0; k < NTASK; k++)
        if (k < 5 || t5) cp_async16(sdst[k] + BUFFLOATS * 4, xb4 + sidx[k], sval[k]);
    cp_commit();

    // ---- 100 reassembly weights -> registers (overlaps in-flight staging) ----
    float wreg[QQ];
    const float* kmp = km + ((size_t)b * QQ * Hc + h) * Wc + w;
    #pragma unroll
    for (int q = 0; q < QQ; q++)
        wreg[q] = __ldg(kmp + (size_t)q * (Hc * Wc));

    float* optr = out + (size_t)b * Cc * 128 * 128
                      + ((size_t)(cbase + (s << 6)) * 128 + 2 * h) * 128 + 2 * w;

    int bufB = 0;   // float offset of current read buffer within warp region

    #pragma unroll 1
    for (int i = 0; i < NITER; i++) {
        if (i < NITER - 1) cp_wait<1>(); else cp_wait<0>();
        __syncwarp();

        // ---- compute CPC channels (25 LDS + 100 FFMA each) ----
        const float* base = wbase + bufB + (lane + 2);
        #pragma unroll
        for (int kch = 0; kch < CPC; kch++) {
            const float* sp = base + kch * (Kk * WROW);
            float a0 = 0.f, a1 = 0.f, a2 = 0.f, a3 = 0.f;
            #pragma unroll
            for (int r = 0; r < Kk; r++) {
                const float* rp = sp + r * WROW;
                float x0 = rp[0], x1 = rp[1], x2 = rp[2], x3 = rp[3], x4 = rp[4];
                const int wb = r * Kk;
                a0 = fmaf(wreg[wb+0],    x0, a0); a0 = fmaf(wreg[wb+1],    x1, a0);
                a0 = fmaf(wreg[wb+2],    x2, a0); a0 = fmaf(wreg[wb+3],    x3, a0);
                a0 = fmaf(wreg[wb+4],    x4, a0);
                a1 = fmaf(wreg[25+wb+0], x0, a1); a1 = fmaf(wreg[25+wb+1], x1, a1);
                a1 = fmaf(wreg[25+wb+2], x2, a1); a1 = fmaf(wreg[25+wb+3], x3, a1);
                a1 = fmaf(wreg[25+wb+4], x4, a1);
                a2 = fmaf(wreg[50+wb+0], x0, a2); a2 = fmaf(wreg[50+wb+1], x1, a2);
                a2 = fmaf(wreg[50+wb+2], x2, a2); a2 = fmaf(wreg[50+wb+3], x3, a2);
                a2 = fmaf(wreg[50+wb+4], x4, a2);
                a3 = fmaf(wreg[75+wb+0], x0, a3); a3 = fmaf(wreg[75+wb+1], x1, a3);
                a3 = fmaf(wreg[75+wb+2], x2, a3); a3 = fmaf(wreg[75+wb+3], x3, a3);
                a3 = fmaf(wreg[75+wb+4], x4, a3);
            }
            // subpixel u = i*2+j -> (2h+i, 2w+j)
            *reinterpret_cast<float2*>(optr)       = make_float2(a0, a1);
            *reinterpret_cast<float2*>(optr + 128) = make_float2(a2, a3);
            optr += 128 * 128;
        }

        // ---- issue group i+2 into the buffer we just finished reading ----
        if (i + 2 < NITER) {
            #pragma unroll
            for (int k = 0; k < NTASK; k++) sidx[k] += CPC * CH4;
            uint32_t dOff = (uint32_t)bufB * 4;
            #pragma unroll
            for (int k = 0; k < NTASK; k++)
                if (k < 5 || t5) cp_async16(sdst[k] + dOff, xb4 + sidx[k], sval[k]);
            cp_commit();
        }
        bufB ^= BUFFLOATS;
    }
}

extern "C" void kernel_launch(void* const* d_in, const int* in_sizes, int n_in,
                              void* d_out, int out_size)
{
    const float* x  = (const float*)d_in[0];   // [8,256,64,64]
    const float* km = (const float*)d_in[1];   // [8,100,64,64]
    float* out = (float*)d_out;                // [8,256,128,128]

    dim3 grid(Bc * Hc, 2);
    carafe_kernel<<<grid, THREADS>>>(x, km, out);
}

// round 10
// speedup vs baseline: 1.0566x; 1.0566x over previous
#include <cuda_runtime.h>
#include <cstdint>

// CARAFE: B=8, C=256, H=W=64, K=5, UP=2.
// out[b,c,2h+i,2w+j] = sum_{ki,kj} km[b,(i*2+j)*25+ki*5+kj,h,w] * x[b,c,h+ki-2,w+kj-2]
//
// R9 vs R7 (60.1us): kill the 2-wave tail (1024 CTAs / 592 slots = 1.73 waves,
// 86.5% efficiency; per-wave time is already AT the 48.4us FFMA floor).
//  - work = 16384 units (unit = bh-row x 8-channel group = one R7 iteration)
//  - 592 persistent CTAs (one wave: 4/SM x 148), static split 28/27 units
//    -> makespan 28 vs 27.68 avg = 98.8% balance
//  - units bh-major: a CTA crosses <=1 bh boundary -> <=2 weight reloads
//  - staging decode collapses: f = tid&15, ci = tid>>4, r = k (no task arrays)
// Compute loop unchanged: 25 LDS + 100 scalar FFMA per channel, weights in regs.

namespace {
constexpr int Hc = 64, Wc = 64, Cc = 256;
constexpr int Kk = 5, QQ = 100;
constexpr int THREADS = 128;
constexpr int SROW = 72;                 // 4 halo + 64 + 4 halo
constexpr int NCH = 8;                   // channels staged per unit
constexpr int NTASK = 5;                 // cp.async16 per thread per unit
constexpr int NBUF = 3;
constexpr int BUFFLOATS = Kk * NCH * SROW;   // 2880
constexpr int BUFBYTES  = BUFFLOATS * 4;     // 11520
constexpr int CH4 = Hc * Wc / 4;             // 1024 float4 per channel image
constexpr int NUNITS = 512 * 32;             // 16384
constexpr int NCTA = 592;                    // 148 SM x 4 CTA -> single wave
constexpr int NBIG = NUNITS - NCTA * 27;     // 400 CTAs take 28 units
}

__device__ __forceinline__ void cp_async16(uint32_t dst, const float4* src, bool valid) {
    int sz = valid ? 16 : 0;
    asm volatile("cp.async.cg.shared.global [%0], [%1], 16, %2;"
                 :: "r"(dst), "l"(src), "r"(sz) : "memory");
}
__device__ __forceinline__ void cp_commit() {
    asm volatile("cp.async.commit_group;" ::: "memory");
}
template <int N>
__device__ __forceinline__ void cp_wait() {
    asm volatile("cp.async.wait_group %0;" :: "n"(N) : "memory");
}

__global__ __launch_bounds__(THREADS, 4)
void carafe_kernel(const float* __restrict__ x,
                   const float* __restrict__ km,
                   float* __restrict__ out)
{
    const int tid = threadIdx.x;
    const int w   = tid & 63;
    const int s   = tid >> 6;            // channel slice 0/1
    const int f   = tid & 15;            // staged float4 column (gc = 4f)
    const int ci  = tid >> 4;            // staged channel index 0..7

    __shared__ __align__(16) float sbuf[NBUF * BUFFLOATS];

    // ---- static work range for this CTA ----
    const int cta = blockIdx.x;
    const int n     = (cta < NBIG) ? 28 : 27;
    const int start = (cta < NBIG) ? cta * 28 : 27 * cta + NBIG;

    // ---- zero halo/pad columns (cols 0..3, 68..71 of all buffers) once ----
    for (int e = tid; e < NBUF * Kk * NCH * 8; e += THREADS) {
        int rc = e >> 3, cs = e & 7;
        int col = (cs < 4) ? cs : (64 + cs);
        sbuf[rc * SROW + col] = 0.f;
    }

    const float4* x4 = (const float4*)x;
    const uint32_t sb_u32 = (uint32_t)__cvta_generic_to_shared(sbuf);
    // per-thread smem byte offset within a buffer for task r=k:
    //   ((k*NCH + ci)*SROW + 4f + 4)*4  = soff0 + k*(NCH*SROW*4)
    const uint32_t soff0 = (uint32_t)((ci * SROW + 4 * f + 4) * 4);

    // ---- issue staging for one unit into buffer bufByte ----
    auto issue = [&](int u, uint32_t bufByte) {
        int bh  = u >> 5;
        int h   = bh & 63;
        int cb  = (bh >> 6) << 8;            // b*256
        int c0  = (u & 31) << 3;
        // global float4 index of task k: chan*CH4 + (h-2+k)*16 + f
        int base4 = (cb + c0 + ci) * CH4 + (h - 2) * 16 + f;
        uint32_t d = sb_u32 + bufByte + soff0;
        #pragma unroll
        for (int k = 0; k < NTASK; k++) {
            bool valid = (unsigned)(h - 2 + k) < (unsigned)Hc;
            cp_async16(d + k * (NCH * SROW * 4), x4 + base4 + k * 16, valid);
        }
        cp_commit();
    };

    // ---- prologue: units start, start+1 (n >= 27 so both exist) ----
    issue(start,     0);
    issue(start + 1, BUFBYTES);

    int cur_bh = -1;
    float wreg[QQ];

    int rdBuf = 0;
    #pragma unroll 1
    for (int j = 0; j < n; j++) {
        const int u  = start + j;
        const int bh = u >> 5;
        const int h  = bh & 63;
        const int b  = bh >> 6;
        const int c0 = (u & 31) << 3;

        if (j < n - 1) cp_wait<1>(); else cp_wait<0>();
        __syncthreads();   // group j visible; readers of j-1 done -> buf[(j+2)%3] free

        if (j + 2 < n) {
            int wrBuf = rdBuf + 2; if (wrBuf >= NBUF) wrBuf -= NBUF;
            issue(u + 2, (uint32_t)wrBuf * BUFBYTES);
        }

        // ---- (re)load this pixel's 100 weights when bh changes ----
        if (bh != cur_bh) {
            cur_bh = bh;
            const float* kmp = km + ((size_t)b * QQ * Hc + h) * Wc + w;
            #pragma unroll
            for (int q = 0; q < QQ; q++)
                wreg[q] = __ldg(kmp + (size_t)q * (Hc * Wc));
        }

        // ---- compute 4 channels (c0 + 4s + kch) for this thread ----
        const float* base = sbuf + rdBuf * BUFFLOATS + (s * 4) * SROW + (w + 2);
        float* optr = out + ((size_t)((b << 8) + c0 + (s << 2)) * 128 + 2 * h) * 128 + 2 * w;
        #pragma unroll
        for (int kch = 0; kch < 4; kch++) {
            const float* sp = base + kch * SROW;
            float a0 = 0.f, a1 = 0.f, a2 = 0.f, a3 = 0.f;
            #pragma unroll
            for (int r = 0; r < Kk; r++) {
                const float* rp = sp + r * (NCH * SROW);
                float x0 = rp[0], x1 = rp[1], x2 = rp[2], x3 = rp[3], x4v = rp[4];
                const int wb = r * Kk;
                a0 = fmaf(wreg[wb+0],    x0, a0); a0 = fmaf(wreg[wb+1],    x1, a0);
                a0 = fmaf(wreg[wb+2],    x2, a0); a0 = fmaf(wreg[wb+3],    x3, a0);
                a0 = fmaf(wreg[wb+4],    x4v, a0);
                a1 = fmaf(wreg[25+wb+0], x0, a1); a1 = fmaf(wreg[25+wb+1], x1, a1);
                a1 = fmaf(wreg[25+wb+2], x2, a1); a1 = fmaf(wreg[25+wb+3], x3, a1);
                a1 = fmaf(wreg[25+wb+4], x4v, a1);
                a2 = fmaf(wreg[50+wb+0], x0, a2); a2 = fmaf(wreg[50+wb+1], x1, a2);
                a2 = fmaf(wreg[50+wb+2], x2, a2); a2 = fmaf(wreg[50+wb+3], x3, a2);
                a2 = fmaf(wreg[50+wb+4], x4v, a2);
                a3 = fmaf(wreg[75+wb+0], x0, a3); a3 = fmaf(wreg[75+wb+1], x1, a3);
                a3 = fmaf(wreg[75+wb+2], x2, a3); a3 = fmaf(wreg[75+wb+3], x3, a3);
                a3 = fmaf(wreg[75+wb+4], x4v, a3);
            }
            // subpixel u = i*2+j -> (2h+i, 2w+j)
            *reinterpret_cast<float2*>(optr)       = make_float2(a0, a1);
            *reinterpret_cast<float2*>(optr + 128) = make_float2(a2, a3);
            optr += 128 * 128;
        }

        rdBuf++; if (rdBuf == NBUF) rdBuf = 0;
    }
}

extern "C" void kernel_launch(void* const* d_in, const int* in_sizes, int n_in,
                              void* d_out, int out_size)
{
    const float* x  = (const float*)d_in[0];   // [8,256,64,64]
    const float* km = (const float*)d_in[1];   // [8,100,64,64]
    float* out = (float*)d_out;                // [8,256,128,128]

    carafe_kernel<<<NCTA, THREADS>>>(x, km, out);
}

// round 11
// speedup vs baseline: 1.1361x; 1.0753x over previous
#include <cuda_runtime.h>
#include <cstdint>

// CARAFE: B=8, C=256, H=W=64, K=5, UP=2.
// out[b,c,2h+i,2w+j] = sum_{ki,kj} km[b,(i*2+j)*25+ki*5+kj,h,w] * x[b,c,h+ki-2,w+kj-2]
//
// R10: single-wave schedule (R9) + R7's clean hot loop.
//  - 592 CTAs, static 28/27 units (unit = bh x 8-channel group), 98.8% balance
//  - CTA range split into <=2 SEGMENTS of constant bh; per segment:
//      * straight-line 100-weight LDG (no in-loop branchy reload -> no ptxas
//        scheduling/regalloc poisoning, R9's suspected 23%/unit regression)
//      * inner loop identical to R7: constant-stride cp.async staging,
//        hoisted row-validity, NBUF=3, one __syncthreads per iteration
//  - segment seam: pipeline drains naturally (wait<0> on last iter) + 1 sync
// Compute loop unchanged: 25 LDS + 100 scalar FFMA per channel, weights in regs.

namespace {
constexpr int Hc = 64, Wc = 64;
constexpr int Kk = 5, QQ = 100;
constexpr int THREADS = 128;
constexpr int SROW = 72;                  // 4 halo + 64 + 4 halo
constexpr int NCH = 8;                    // channels staged per unit
constexpr int NBUF = 3;
constexpr int BUFFLOATS = Kk * NCH * SROW;    // 2880
constexpr int BUFBYTES  = BUFFLOATS * 4;      // 11520
constexpr int ROWB = NCH * SROW * 4;          // smem bytes between kernel rows
constexpr int CH4 = Hc * Wc / 4;              // 1024 float4 per channel image
constexpr int NUNITS = 512 * 32;              // 16384
constexpr int NCTA = 592;                     // <= SMs*4 on both 148/152-SM parts
constexpr int NBIG = NUNITS - NCTA * 27;      // 400 CTAs take 28 units
constexpr int U4 = NCH * CH4;                 // float4 stride of one unit (8 ch)
}

__device__ __forceinline__ void cp_async16(uint32_t dst, const float4* src, bool valid) {
    int sz = valid ? 16 : 0;
    asm volatile("cp.async.cg.shared.global [%0], [%1], 16, %2;"
                 :: "r"(dst), "l"(src), "r"(sz) : "memory");
}
__device__ __forceinline__ void cp_commit() {
    asm volatile("cp.async.commit_group;" ::: "memory");
}
template <int N>
__device__ __forceinline__ void cp_wait() {
    asm volatile("cp.async.wait_group %0;" :: "n"(N) : "memory");
}

__global__ __launch_bounds__(THREADS, 4)
void carafe_kernel(const float* __restrict__ x,
                   const float* __restrict__ km,
                   float* __restrict__ out)
{
    const int tid = threadIdx.x;
    const int w   = tid & 63;
    const int s   = tid >> 6;            // channel slice 0/1
    const int f   = tid & 15;            // staged float4 column (gc = 4f)
    const int ci  = tid >> 4;            // staged channel index 0..7

    __shared__ __align__(16) float sbuf[NBUF * BUFFLOATS];

    // ---- static work range ----
    const int cta   = blockIdx.x;
    const int n     = (cta < NBIG) ? 28 : 27;
    const int start = (cta < NBIG) ? cta * 28 : 27 * cta + NBIG;

    // ---- zero halo/pad columns (cols 0..3, 68..71 of all buffers) once ----
    for (int e = tid; e < NBUF * Kk * NCH * 8; e += THREADS) {
        int rc = e >> 3, cs = e & 7;
        int col = (cs < 4) ? cs : (64 + cs);
        sbuf[rc * SROW + col] = 0.f;
    }

    const float4* x4 = (const float4*)x;
    const uint32_t sb_u32 = (uint32_t)__cvta_generic_to_shared(sbuf);
    const uint32_t soff0  = (uint32_t)((ci * SROW + 4 * f + 4) * 4);

    int u = start, rem = n;
    bool first = true;

    #pragma unroll 1
    while (rem > 0) {
        const int bh = u >> 5;
        const int g0 = u & 31;
        const int b  = bh >> 6;
        const int h  = bh & 63;
        int cnt = 32 - g0; if (cnt > rem) cnt = rem;

        // protect buffers from the previous segment's readers (pipeline already
        // drained by its final wait<0>)
        if (!first) __syncthreads();
        first = false;

        // ---- hoisted per-segment staging constants (h fixed) ----
        bool rv[Kk]; int rb[Kk];
        #pragma unroll
        for (int k = 0; k < Kk; k++) {
            int gr = h - 2 + k;
            rv[k] = (unsigned)gr < (unsigned)Hc;
            rb[k] = (rv[k] ? gr : 0) * (Wc / 4) + f;
        }
        int cb4 = ((b << 8) + (g0 << 3) + ci) * CH4;   // += U4 per unit

        // ---- prologue: issue groups 0 (+1) ----
        #pragma unroll
        for (int k = 0; k < Kk; k++)
            cp_async16(sb_u32 + soff0 + k * ROWB, x4 + cb4 + rb[k], rv[k]);
        cp_commit();
        if (cnt > 1) {
            #pragma unroll
            for (int k = 0; k < Kk; k++)
                cp_async16(sb_u32 + BUFBYTES + soff0 + k * ROWB,
                           x4 + (cb4 + U4) + rb[k], rv[k]);
            cp_commit();
        }

        // ---- weights for this bh (straight-line, overlaps in-flight staging) ----
        float wreg[QQ];
        const float* kmp = km + ((size_t)b * QQ * Hc + h) * Wc + w;
        #pragma unroll
        for (int q = 0; q < QQ; q++)
            wreg[q] = __ldg(kmp + (size_t)q * (Hc * Wc));

        float* optr = out + ((size_t)((b << 8) + (g0 << 3) + (s << 2)) * 128
                             + 2 * h) * 128 + 2 * w;
        int cb4i = cb4 + 2 * U4;   // group j+2 base
        int rdBuf = 0;

        #pragma unroll 1
        for (int j = 0; j < cnt; j++) {
            if (j + 1 < cnt) cp_wait<1>(); else cp_wait<0>();
            __syncthreads();   // group j visible; readers of j-1 done

            if (j + 2 < cnt) {
                int wr = rdBuf + 2; if (wr >= NBUF) wr -= NBUF;
                uint32_t d = sb_u32 + (uint32_t)wr * BUFBYTES + soff0;
                #pragma unroll
                for (int k = 0; k < Kk; k++)
                    cp_async16(d + k * ROWB, x4 + cb4i + rb[k], rv[k]);
                cp_commit();
                cb4i += U4;
            }

            // ---- compute 4 channels (R7 body) ----
            const float* base = sbuf + rdBuf * BUFFLOATS + (s * 4) * SROW + (w + 2);
            #pragma unroll
            for (int kch = 0; kch < 4; kch++) {
                const float* sp = base + kch * SROW;
                float a0 = 0.f, a1 = 0.f, a2 = 0.f, a3 = 0.f;
                #pragma unroll
                for (int r = 0; r < Kk; r++) {
                    const float* rp = sp + r * (NCH * SROW);
                    float x0 = rp[0], x1 = rp[1], x2 = rp[2], x3 = rp[3], x4v = rp[4];
                    const int wb = r * Kk;
                    a0 = fmaf(wreg[wb+0],    x0, a0); a0 = fmaf(wreg[wb+1],    x1, a0);
                    a0 = fmaf(wreg[wb+2],    x2, a0); a0 = fmaf(wreg[wb+3],    x3, a0);
                    a0 = fmaf(wreg[wb+4],    x4v, a0);
                    a1 = fmaf(wreg[25+wb+0], x0, a1); a1 = fmaf(wreg[25+wb+1], x1, a1);
                    a1 = fmaf(wreg[25+wb+2], x2, a1); a1 = fmaf(wreg[25+wb+3], x3, a1);
                    a1 = fmaf(wreg[25+wb+4], x4v, a1);
                    a2 = fmaf(wreg[50+wb+0], x0, a2); a2 = fmaf(wreg[50+wb+1], x1, a2);
                    a2 = fmaf(wreg[50+wb+2], x2, a2); a2 = fmaf(wreg[50+wb+3], x3, a2);
                    a2 = fmaf(wreg[50+wb+4], x4v, a2);
                    a3 = fmaf(wreg[75+wb+0], x0, a3); a3 = fmaf(wreg[75+wb+1], x1, a3);
                    a3 = fmaf(wreg[75+wb+2], x2, a3); a3 = fmaf(wreg[75+wb+3], x3, a3);
                    a3 = fmaf(wreg[75+wb+4], x4v, a3);
                }
                // subpixel u = i*2+j -> (2h+i, 2w+j)
                float* o = optr + (size_t)kch * (128 * 128);
                *reinterpret_cast<float2*>(o)       = make_float2(a0, a1);
                *reinterpret_cast<float2*>(o + 128) = make_float2(a2, a3);
            }
            optr += (size_t)NCH * (128 * 128);

            rdBuf++; if (rdBuf == NBUF) rdBuf = 0;
        }

        u += cnt; rem -= cnt;
    }
}

extern "C" void kernel_launch(void* const* d_in, const int* in_sizes, int n_in,
                              void* d_out, int out_size)
{
    const float* x  = (const float*)d_in[0];   // [8,256,64,64]
    const float* km = (const float*)d_in[1];   // [8,100,64,64]
    float* out = (float*)d_out;                // [8,256,128,128]

    carafe_kernel<<<NCTA, THREADS>>>(x, km, out);
}

// round 12
// speedup vs baseline: 1.1772x; 1.0361x over previous
#include <cuda_runtime.h>
#include <cstdint>

// CARAFE: B=8, C=256, H=W=64, K=5, UP=2.
// out[b,c,2h+i,2w+j] = sum_{ki,kj} km[b,(i*2+j)*25+ki*5+kj,h,w] * x[b,c,h+ki-2,w+kj-2]
//
// R11 vs R10 (57.8us): split each CTA into TWO fully independent 64-thread
// groups (group g stages AND computes channels [c0+4g, c0+4g+4) in its own
// private smem buffers) -> replace __syncthreads with named bar.sync(g+1, 64).
// Halves the lockstep domain; warp-pairs drift and cover each other's bubbles.
// Everything else identical to R10: 592 CTAs single-wave static 28/27 split,
// <=2 constant-bh segments, NBUF=3 cp.async pipeline, 25 LDS + 100 FFMA/channel.

namespace {
constexpr int Hc = 64, Wc = 64;
constexpr int Kk = 5, QQ = 100;
constexpr int THREADS = 128;
constexpr int SROW = 72;                  // 4 halo + 64 + 4 halo
constexpr int GCH = 4;                    // channels per group per unit
constexpr int NBUF = 3;
constexpr int GBUF  = Kk * GCH * SROW;    // 1440 floats per group-buffer
constexpr int GBUFB = GBUF * 4;           // 5760 B
constexpr int GROWB = GCH * SROW * 4;     // smem bytes between kernel rows
constexpr int CH4 = Hc * Wc / 4;          // 1024 float4 per channel image
constexpr int NUNITS = 512 * 32;          // 16384
constexpr int NCTA = 592;                 // single wave on 148-152 SMs x 4 CTA
constexpr int NBIG = NUNITS - NCTA * 27;  // 400 CTAs take 28 units
constexpr int U4 = 8 * CH4;               // float4 stride of one unit (8 ch)
}

__device__ __forceinline__ void cp_async16(uint32_t dst, const float4* src, bool valid) {
    int sz = valid ? 16 : 0;
    asm volatile("cp.async.cg.shared.global [%0], [%1], 16, %2;"
                 :: "r"(dst), "l"(src), "r"(sz) : "memory");
}
__device__ __forceinline__ void cp_commit() {
    asm volatile("cp.async.commit_group;" ::: "memory");
}
template <int N>
__device__ __forceinline__ void cp_wait() {
    asm volatile("cp.async.wait_group %0;" :: "n"(N) : "memory");
}
__device__ __forceinline__ void group_bar(int id) {
    asm volatile("bar.sync %0, 64;" :: "r"(id) : "memory");
}

__global__ __launch_bounds__(THREADS, 4)
void carafe_kernel(const float* __restrict__ x,
                   const float* __restrict__ km,
                   float* __restrict__ out)
{
    const int tid = threadIdx.x;
    const int g   = tid >> 6;            // independent 64-thread group 0/1
    const int w   = tid & 63;            // pixel column (compute role)
    const int f   = tid & 15;            // staged float4 column (staging role)
    const int cig = (tid >> 4) & 3;      // staged channel within group

    // two groups x NBUF buffers x [Kk][GCH][SROW]
    __shared__ __align__(16) float sbuf[2 * NBUF * GBUF];

    float* sgrp = sbuf + g * (NBUF * GBUF);

    // ---- static work range ----
    const int cta   = blockIdx.x;
    const int n     = (cta < NBIG) ? 28 : 27;
    const int start = (cta < NBIG) ? cta * 28 : 27 * cta + NBIG;

    // ---- zero halo/pad columns of THIS group's buffers (group-local, once) ----
    // rows: NBUF*Kk*GCH = 60 channel-rows, 8 pad cols each (0..3, 68..71)
    for (int e = (tid & 63); e < NBUF * Kk * GCH * 8; e += 64) {
        int rc = e >> 3, cs = e & 7;
        int col = (cs < 4) ? cs : (64 + cs);
        sgrp[rc * SROW + col] = 0.f;
    }

    const float4* x4 = (const float4*)x;
    const uint32_t sg_u32 = (uint32_t)__cvta_generic_to_shared(sgrp);
    const uint32_t soff0  = (uint32_t)((cig * SROW + 4 * f + 4) * 4);

    int u = start, rem = n;
    bool first = true;

    #pragma unroll 1
    while (rem > 0) {
        const int bh = u >> 5;
        const int g0 = u & 31;
        const int b  = bh >> 6;
        const int h  = bh & 63;
        int cnt = 32 - g0; if (cnt > rem) cnt = rem;

        // protect this group's buffers from its previous-segment readers
        if (!first) group_bar(g + 1);
        first = false;

        // ---- hoisted per-segment staging constants (h fixed) ----
        bool rv[Kk]; int rb[Kk];
        #pragma unroll
        for (int k = 0; k < Kk; k++) {
            int gr = h - 2 + k;
            rv[k] = (unsigned)gr < (unsigned)Hc;
            rb[k] = (rv[k] ? gr : 0) * (Wc / 4) + f;
        }
        // this group's staged channel: c0 + 4g + cig
        int cb4 = ((b << 8) + (g0 << 3) + (g << 2) + cig) * CH4;   // += U4 per unit

        // ---- prologue: issue groups 0 (+1) ----
        #pragma unroll
        for (int k = 0; k < Kk; k++)
            cp_async16(sg_u32 + soff0 + k * GROWB, x4 + cb4 + rb[k], rv[k]);
        cp_commit();
        if (cnt > 1) {
            #pragma unroll
            for (int k = 0; k < Kk; k++)
                cp_async16(sg_u32 + GBUFB + soff0 + k * GROWB,
                           x4 + (cb4 + U4) + rb[k], rv[k]);
            cp_commit();
        }

        // ---- weights for this bh (straight-line, overlaps in-flight staging) ----
        float wreg[QQ];
        const float* kmp = km + ((size_t)b * QQ * Hc + h) * Wc + w;
        #pragma unroll
        for (int q = 0; q < QQ; q++)
            wreg[q] = __ldg(kmp + (size_t)q * (Hc * Wc));

        float* optr = out + ((size_t)((b << 8) + (g0 << 3) + (g << 2)) * 128
                             + 2 * h) * 128 + 2 * w;
        int cb4i = cb4 + 2 * U4;   // unit j+2 base
        int rdBuf = 0;

        #pragma unroll 1
        for (int j = 0; j < cnt; j++) {
            if (j + 1 < cnt) cp_wait<1>(); else cp_wait<0>();
            group_bar(g + 1);   // group j data visible; group readers of j-1 done

            if (j + 2 < cnt) {
                int wr = rdBuf + 2; if (wr >= NBUF) wr -= NBUF;
                uint32_t d = sg_u32 + (uint32_t)wr * GBUFB + soff0;
                #pragma unroll
                for (int k = 0; k < Kk; k++)
                    cp_async16(d + k * GROWB, x4 + cb4i + rb[k], rv[k]);
                cp_commit();
                cb4i += U4;
            }

            // ---- compute this group's 4 channels ----
            const float* base = sgrp + rdBuf * GBUF + (w + 2);
            #pragma unroll
            for (int kch = 0; kch < GCH; kch++) {
                const float* sp = base + kch * SROW;
                float a0 = 0.f, a1 = 0.f, a2 = 0.f, a3 = 0.f;
                #pragma unroll
                for (int r = 0; r < Kk; r++) {
                    const float* rp = sp + r * (GCH * SROW);
                    float x0 = rp[0], x1 = rp[1], x2 = rp[2], x3 = rp[3], x4v = rp[4];
                    const int wb = r * Kk;
                    a0 = fmaf(wreg[wb+0],    x0, a0); a0 = fmaf(wreg[wb+1],    x1, a0);
                    a0 = fmaf(wreg[wb+2],    x2, a0); a0 = fmaf(wreg[wb+3],    x3, a0);
                    a0 = fmaf(wreg[wb+4],    x4v, a0);
                    a1 = fmaf(wreg[25+wb+0], x0, a1); a1 = fmaf(wreg[25+wb+1], x1, a1);
                    a1 = fmaf(wreg[25+wb+2], x2, a1); a1 = fmaf(wreg[25+wb+3], x3, a1);
                    a1 = fmaf(wreg[25+wb+4], x4v, a1);
                    a2 = fmaf(wreg[50+wb+0], x0, a2); a2 = fmaf(wreg[50+wb+1], x1, a2);
                    a2 = fmaf(wreg[50+wb+2], x2, a2); a2 = fmaf(wreg[50+wb+3], x3, a2);
                    a2 = fmaf(wreg[50+wb+4], x4v, a2);
                    a3 = fmaf(wreg[75+wb+0], x0, a3); a3 = fmaf(wreg[75+wb+1], x1, a3);
                    a3 = fmaf(wreg[75+wb+2], x2, a3); a3 = fmaf(wreg[75+wb+3], x3, a3);
                    a3 = fmaf(wreg[75+wb+4], x4v, a3);
                }
                // subpixel u = i*2+j -> (2h+i, 2w+j)
                float* o = optr + (size_t)kch * (128 * 128);
                *reinterpret_cast<float2*>(o)       = make_float2(a0, a1);
                *reinterpret_cast<float2*>(o + 128) = make_float2(a2, a3);
            }
            optr += (size_t)8 * (128 * 128);

            rdBuf++; if (rdBuf == NBUF) rdBuf = 0;
        }

        u += cnt; rem -= cnt;
    }
}

extern "C" void kernel_launch(void* const* d_in, const int* in_sizes, int n_in,
                              void* d_out, int out_size)
{
    const float* x  = (const float*)d_in[0];   // [8,256,64,64]
    const float* km = (const float*)d_in[1];   // [8,100,64,64]
    float* out = (float*)d_out;                // [8,256,128,128]

    carafe_kernel<<<NCTA, THREADS>>>(x, km, out);
}